// round 11
// baseline (speedup 1.0000x reference)
#include <cuda_runtime.h>

#define DB 160
#define HB 160
#define WB 160
#define NB 2
#define NTOT (NB*DB*HB*WB)              // 8,192,000
#define PW (WB/32)                       // 5 packed words per row
#define NWORDS (NTOT/32)                 // 256,000 words
#define TPB 256
#define PACK_EPT 4
#define PACK_BLOCKS (NTOT/(TPB*PACK_EPT))// 8000
#define WORD_BLOCKS (NWORDS/TPB)         // 1000

// acc[0]=sum (1+w)*bce, acc[1]=sum p, acc[2]=sum p*t, acc[3]=sum t
__device__ double g_acc[4];
__device__ unsigned g_count;
__device__ unsigned g_packed[NWORDS];
__device__ unsigned g_nib[NTOT/8 + 4];   // 4-bit neighbour nibbles + pad

// ---------------- pack via warp ballot -----------------------------------
__global__ __launch_bounds__(TPB) void pack_kernel(const int* __restrict__ target) {
    if (blockIdx.x == 0 && threadIdx.x < 4) g_acc[threadIdx.x] = 0.0;
    const int tid  = blockIdx.x * TPB + threadIdx.x;
    const int lane = threadIdx.x & 31;
    const int gw   = tid >> 5;
    const int ebase = gw * 32 * PACK_EPT;
    unsigned keep = 0u;
    #pragma unroll
    for (int i = 0; i < PACK_EPT; i++) {
        const int v = target[ebase + i * 32 + lane];
        const unsigned w = __ballot_sync(0xffffffffu, v != 0);
        if (lane == i) keep = w;
    }
    if (lane < PACK_EPT) g_packed[gw * PACK_EPT + lane] = keep;
}

// ---------------- code: masks -> interleaved nibbles ----------------------
// nibble e = t00[e] | t01[e]<<1 | t10[e]<<2 | t11[e]<<3, gated to 0 on
// non-interior (d==159 || h==159) rows.
__global__ __launch_bounds__(TPB) void code_kernel() {
    __shared__ unsigned s_spread[256];    // byte b -> bits at positions 4i
    {
        unsigned b = threadIdx.x, s = 0u;
        #pragma unroll
        for (int i = 0; i < 8; i++) s |= ((b >> i) & 1u) << (4 * i);
        s_spread[threadIdx.x] = s;
    }
    __syncthreads();

    const int t = blockIdx.x * TPB + threadIdx.x;   // word id
    int r        = t / PW;
    const int h  = r % HB;
    r            = r / HB;
    const int d  = r % DB;
    const bool interior = (d < DB - 1) && (h < HB - 1);

    unsigned m00 = 0u, m01 = 0u, m10 = 0u, m11 = 0u;
    if (interior) {
        m00 = g_packed[t];
        m01 = g_packed[t + PW];
        m10 = g_packed[t + HB * PW];
        m11 = g_packed[t + HB * PW + PW];
    }
    uint4 outv;
    unsigned* o = (unsigned*)&outv;
    #pragma unroll
    for (int seg = 0; seg < 4; seg++) {
        o[seg] = s_spread[(m00 >> (8 * seg)) & 0xFFu]
               | (s_spread[(m01 >> (8 * seg)) & 0xFFu] << 1)
               | (s_spread[(m10 >> (8 * seg)) & 0xFFu] << 2)
               | (s_spread[(m11 >> (8 * seg)) & 0xFFu] << 3);
    }
    *(uint4*)(g_nib + 4 * t) = outv;
}

// XOR swizzle on float4 index within a warp's 256-float4 tile.
__device__ __forceinline__ int swz(int idx16) { return idx16 ^ ((idx16 >> 3) & 7); }

// ---------------- main: fused loss, 32 elts/thread ------------------------
__global__ __launch_bounds__(TPB) void loss_main_kernel(
    const float* __restrict__ logits,
    const float* __restrict__ area_table,
    float* __restrict__ out)
{
    __shared__ float4 s_tile[TPB * 8];     // 32 KB: per-warp 4 KB logits tiles
    __shared__ float s_area3[256];
    __shared__ float s_red[4][TPB / 32];

    // Table indexed by the nibble-pair byte b:
    //   b0=t00[e] b1=t01[e] b2=t10[e] b3=t11[e] b4=t00[e+1] b5=t01[e+1] b6=t10[e+1] b7=t11[e+1]
    // Stores 1 + area_table[reference_code]; b==0 -> 1 (boundary gating free).
    {
        const unsigned b = (unsigned)threadIdx.x;
        const unsigned ref = ((b & 1u) << 7) | (((b >> 4) & 1u) << 6)
                           | (((b >> 1) & 1u) << 5) | (((b >> 5) & 1u) << 4)
                           | (((b >> 2) & 1u) << 3) | (((b >> 6) & 1u) << 2)
                           | (((b >> 3) & 1u) << 1) | ((b >> 7) & 1u);
        s_area3[b] = 1.f + area_table[ref];
    }
    __syncthreads();

    const int lane = threadIdx.x & 31;
    const int warp = threadIdx.x >> 5;
    const int t  = blockIdx.x * TPB + threadIdx.x;            // word id
    const bool hiok = (t % PW) < (PW - 1);

    // ---- COALESCED logits load -> swizzled per-warp smem tile ----
    {
        const float4* __restrict__ lg4 = (const float4*)logits;
        const int gbase = blockIdx.x * (TPB * 8) + warp * 256;   // float4 units
        float4 v[4];
        #pragma unroll
        for (int k = 0; k < 4; k++) v[k] = lg4[gbase + k * 32 + lane];
        #pragma unroll
        for (int k = 0; k < 4; k++) s_tile[warp * 256 + swz(k * 32 + lane)] = v[k];
        #pragma unroll
        for (int k = 4; k < 8; k++) v[k - 4] = lg4[gbase + k * 32 + lane];
        #pragma unroll
        for (int k = 4; k < 8; k++) s_tile[warp * 256 + swz(k * 32 + lane)] = v[k - 4];
    }

    const unsigned m00lo = g_packed[t];
    // Nibble array: 16 bytes (32 nibbles) + first nibble of next word for e=31.
    unsigned nreg[5];
    {
        const uint4 nb = *(const uint4*)(g_nib + 4 * t);
        nreg[0] = nb.x; nreg[1] = nb.y; nreg[2] = nb.z; nreg[3] = nb.w;
        nreg[4] = g_nib[4 * t + 4];
    }

    __syncwarp();   // tile is warp-private

    float acc_wbce = 0.f, acc_p = 0.f, acc_pt = 0.f;
    const float acc_t = (float)__popc(m00lo);

    #pragma unroll
    for (int q = 0; q < 8; q++) {
        const float4 xq = s_tile[warp * 256 + swz(lane * 8 + q)];
        const float xs[4] = {xq.x, xq.y, xq.z, xq.w};
        #pragma unroll
        for (int e2 = 0; e2 < 4; e2++) {
            const int e = q * 4 + e2;
            const float xv = xs[e2];
            const bool bit = ((m00lo >> e) & 1u) != 0u;

            // z = e^{-x}; s = 1+z; p = 1/s; bce = x*(1-t) + ln(s)
            const float z = exp2f(-1.442695041f * xv);
            const float s = 1.f + z;
            float p;
            asm("rcp.approx.f32 %0, %1;" : "=f"(p) : "f"(s));
            const float l2s = __log2f(s);
            const float xnt = bit ? 0.f : xv;
            const float bce = fmaf(0.693147181f, l2s, xnt);

            // code byte = nib_e | nib_{e+1}<<4 (all shifts compile-time)
            const int ri = e >> 3;
            const int sh = 4 * (e & 7);
            unsigned code;
            if (sh <= 24) code = (nreg[ri] >> sh) & 0xFFu;
            else          code = __funnelshift_r(nreg[ri], nreg[ri + 1], 28) & 0xFFu;
            float wa1 = s_area3[code];                  // = 1 + weight
            if (e == 31 && !hiok) wa1 = 1.f;            // w==159 column: weight 0

            acc_wbce = fmaf(wa1, bce, acc_wbce);
            acc_p += p;
            if (bit) acc_pt += p;
        }
    }

    // ---- block reduction ----
    float v0 = acc_wbce, v1 = acc_p, v2 = acc_pt, v3 = acc_t;
    #pragma unroll
    for (int off = 16; off > 0; off >>= 1) {
        v0 += __shfl_xor_sync(0xffffffffu, v0, off);
        v1 += __shfl_xor_sync(0xffffffffu, v1, off);
        v2 += __shfl_xor_sync(0xffffffffu, v2, off);
        v3 += __shfl_xor_sync(0xffffffffu, v3, off);
    }
    if (lane == 0) { s_red[0][warp] = v0; s_red[1][warp] = v1; s_red[2][warp] = v2; s_red[3][warp] = v3; }
    __syncthreads();
    if (warp == 0) {
        const int nw = TPB / 32;
        v0 = (lane < nw) ? s_red[0][lane] : 0.f;
        v1 = (lane < nw) ? s_red[1][lane] : 0.f;
        v2 = (lane < nw) ? s_red[2][lane] : 0.f;
        v3 = (lane < nw) ? s_red[3][lane] : 0.f;
        #pragma unroll
        for (int off = 4; off > 0; off >>= 1) {
            v0 += __shfl_xor_sync(0xffffffffu, v0, off);
            v1 += __shfl_xor_sync(0xffffffffu, v1, off);
            v2 += __shfl_xor_sync(0xffffffffu, v2, off);
            v3 += __shfl_xor_sync(0xffffffffu, v3, off);
        }
        if (lane == 0) {
            atomicAdd(&g_acc[0], (double)v0);
            atomicAdd(&g_acc[1], (double)v1);
            atomicAdd(&g_acc[2], (double)v2);
            atomicAdd(&g_acc[3], (double)v3);
            __threadfence();
            const unsigned old = atomicAdd(&g_count, 1u);
            if (old == WORD_BLOCKS - 1) {
                const double a0 = atomicAdd(&g_acc[0], 0.0);
                const double a1 = atomicAdd(&g_acc[1], 0.0);
                const double a2 = atomicAdd(&g_acc[2], 0.0);
                const double a3 = atomicAdd(&g_acc[3], 0.0);
                const double wbce = a0 / (double)NTOT;
                const double dice = 1.0 - (2.0 * a2 + 1.0) / (a1 + a3 + 1.0);
                out[0] = (float)(wbce + dice);
                g_count = 0u;    // g_acc re-zeroed by next pack launch
                __threadfence();
            }
        }
    }
}

extern "C" void kernel_launch(void* const* d_in, const int* in_sizes, int n_in,
                              void* d_out, int out_size) {
    const float* logits     = (const float*)d_in[0];
    const int*   target     = (const int*)d_in[1];
    const float* area_table = (const float*)d_in[2];
    float* out = (float*)d_out;

    pack_kernel<<<PACK_BLOCKS, TPB>>>(target);
    code_kernel<<<WORD_BLOCKS, TPB>>>();
    loss_main_kernel<<<WORD_BLOCKS, TPB>>>(logits, area_table, out);
}